// round 15
// baseline (speedup 1.0000x reference)
#include <cuda_runtime.h>
#include <cuda.h>
#include <cuda_fp16.h>
#include <math.h>
#include <stdint.h>

#define N_NODES 6144
#define D_IN    256
#define HID     64
#define OUT_DIM 32
#define ATT_H   128

#define ADJ_SCALE   2048.0f
#define ADJ_UNSCALE 4.8828125e-4f   // 1/2048

// ---------------- scratch (device globals; no allocation allowed) ----------
__device__ uint32_t g_h0p[N_NODES * HID / 2];
__device__ uint32_t g_h1p[N_NODES * HID / 2];
__device__ uint32_t g_ictp[N_NODES * HID / 2];
__device__ float g_part[10 * N_NODES * HID];
__device__ float g_z[5 * N_NODES * HID];
__device__ float g_zii[2 * N_NODES * HID];
__device__ float g_relagg  [N_NODES * HID];
__device__ float g_itemitem[N_NODES * HID];

// ---------------- helpers -----------------------------------------------------
__device__ __forceinline__ uint32_t smem_u32(const void* p) {
    uint32_t a;
    asm("{ .reg .u64 t; cvta.to.shared.u64 t, %1; cvt.u32.u64 %0, t; }"
        : "=r"(a) : "l"(p));
    return a;
}
__device__ __forceinline__ float tanha(float x) {
    float y;
    asm("tanh.approx.f32 %0, %1;" : "=f"(y) : "f"(x));
    return y;
}
__device__ __forceinline__ uint32_t pack_f16x2(float lo, float hi) {
    uint32_t r;
    asm("cvt.rn.f16x2.f32 %0, %1, %2;" : "=r"(r) : "f"(hi), "f"(lo));
    return r;
}
__device__ __forceinline__ void mma_fp16(float* c, const uint32_t* a, const uint32_t* b) {
    asm("mma.sync.aligned.m16n8k16.row.col.f32.f16.f16.f32 "
        "{%0,%1,%2,%3}, {%4,%5,%6,%7}, {%8,%9}, {%0,%1,%2,%3};"
        : "+f"(c[0]), "+f"(c[1]), "+f"(c[2]), "+f"(c[3])
        : "r"(a[0]), "r"(a[1]), "r"(a[2]), "r"(a[3]),
          "r"(b[0]), "r"(b[1]));
}
__device__ __forceinline__ void cp16(void* dst, const void* src) {
    uint32_t d = (uint32_t)__cvta_generic_to_shared(dst);
    asm volatile("cp.async.cg.shared.global [%0], [%1], 16;" :: "r"(d), "l"(src));
}
__device__ __forceinline__ void cp_commit() {
    asm volatile("cp.async.commit_group;" ::: "memory");
}
__device__ __forceinline__ void cp_wait1() {
    asm volatile("cp.async.wait_group 1;" ::: "memory");
}
__device__ __forceinline__ void mbar_init(uint32_t addr, uint32_t cnt) {
    asm volatile("mbarrier.init.shared.b64 [%0], %1;" :: "r"(addr), "r"(cnt) : "memory");
}
__device__ __forceinline__ void mbar_expect_tx(uint32_t addr, uint32_t bytes) {
    asm volatile("mbarrier.arrive.expect_tx.shared.b64 _, [%0], %1;"
                 :: "r"(addr), "r"(bytes) : "memory");
}
__device__ __forceinline__ void mbar_wait(uint32_t addr, uint32_t parity) {
    uint32_t done;
    asm volatile(
        "{ .reg .pred p; mbarrier.try_wait.parity.acquire.cta.shared::cta.b64 p, [%1], %2;"
        " selp.b32 %0, 1, 0, p; }"
        : "=r"(done) : "r"(addr), "r"(parity) : "memory");
    if (!done) {
        asm volatile(
            "{ .reg .pred P1;\n"
            "WL_%=: mbarrier.try_wait.parity.acquire.cta.shared::cta.b64 P1, [%0], %1, 0x989680;\n"
            "@P1 bra.uni WD_%=;\n"
            "bra.uni WL_%=;\n"
            "WD_%=: }"
            :: "r"(addr), "r"(parity) : "memory");
    }
}
__device__ __forceinline__ void tma_load_a(
    const CUtensorMap* tm, uint32_t dst, int x, int y, int z, uint32_t mbar)
{
    asm volatile(
        "cp.async.bulk.tensor.3d.shared::cta.global.tile.mbarrier::complete_tx::bytes "
        "[%0], [%1, {%2, %3, %4}], [%5];"
        :: "r"(dst), "l"(tm), "r"(x), "r"(y), "r"(z), "r"(mbar)
        : "memory");
}

// ---------------- feature mapping + fp16 pack --------------------------------
__global__ void __launch_bounds__(256) map_kernel(
    const float* __restrict__ feat, const float* __restrict__ W,
    const float* __restrict__ b, uint32_t* __restrict__ outp)
{
    __shared__ float hs[4][HID];
    int tx = threadIdx.x, ty = threadIdx.y;
    int row = blockIdx.x * 4 + ty;
    const float* fr = feat + (size_t)row * D_IN;
    float acc = b[tx];
#pragma unroll 8
    for (int k = 0; k < D_IN; k++)
        acc = fmaf(fr[k], W[k * HID + tx], acc);
    hs[ty][tx] = tanhf(acc);
    __syncthreads();
    int tid = ty * 64 + tx;
    if (tid < 128) {
        int pr = tid >> 6, c = tid & 63;
        outp[(size_t)(blockIdx.x * 2 + pr) * HID + c] =
            pack_f16x2(hs[2 * pr][c], hs[2 * pr + 1][c]);
    }
}

// ---------------- big GEMM: SWIZZLE_NONE TMA (768B rows) + fp16 restage ------
// BM=64 rows, BKO=192 cols/tile. 256 threads = 8 warps (4M x 2N), warp 16x32.
#define BM 64
#define BKO 192
#define A16_STRIDE 100               // u32 words per fp16 A row (padded, CF frags)
#define HS_STRIDE 72
#define A_RAW_STAGE 49152            // 64 rows x 768B
#define A16_BYTES (BM * A16_STRIDE * 4)
#define H_STAGE_WORDS (96 * HS_STRIDE)
#define H_STAGE_BYTES (H_STAGE_WORDS * 4)
#define ARAW_OFF 1024
#define A16_OFF  (ARAW_OFF + 2 * A_RAW_STAGE)
#define H_OFF    (A16_OFF + A16_BYTES)
#define SPMM_SMEM_BYTES (H_OFF + 2 * H_STAGE_BYTES)   // 180224

__device__ __forceinline__ void spmm_load_h(
    const uint32_t* __restrict__ Hp, uint32_t* hs, int k0, int tid)
{
#pragma unroll
    for (int i = 0; i < 6; i++) {
        int idx = tid + i * 256;           // 0..1535
        int r   = idx >> 4;                // pair-row 0..95
        int c4  = (idx & 15) << 2;
        cp16(hs + r * HS_STRIDE + c4, Hp + (size_t)((k0 >> 1) + r) * HID + c4);
    }
}

__global__ void __launch_bounds__(256, 1) spmm_kernel(
    const __grid_constant__ CUtensorMap tmA,
    const __grid_constant__ CUtensorMap tmB,
    int nA, const uint32_t* __restrict__ hA, const uint32_t* __restrict__ hB,
    float* __restrict__ part, int kPerSplit)
{
    extern __shared__ __align__(1024) char smem[];
    uint32_t sbase = smem_u32(smem);

    int b = blockIdx.y;
    const CUtensorMap* tm;
    const uint32_t* Hp;
    int zc;
    if (b < nA) { tm = &tmA; zc = b;      Hp = hA; }
    else        { tm = &tmB; zc = b - nA; Hp = hB; }

    float* Cb = part + ((size_t)blockIdx.z * gridDim.y + b) * (size_t)(N_NODES * HID);
    uint32_t* HsBase = (uint32_t*)(smem + H_OFF);
    uint32_t* a16    = (uint32_t*)(smem + A16_OFF);

    int tid  = threadIdx.x;
    int lane = tid & 31;
    int warp = tid >> 5;
    int g = lane >> 2;
    int t = lane & 3;
    int wm = (warp & 3) * 16;
    int wn = (warp >> 2) * 32;
    int row0 = blockIdx.x * BM;
    int kbeg = blockIdx.z * kPerSplit;
    int nt = kPerSplit / BKO;

    if (tid == 0) { mbar_init(sbase, 1); mbar_init(sbase + 8, 1); }
    __syncthreads();

    float acc[4][4];
#pragma unroll
    for (int ntl = 0; ntl < 4; ntl++)
#pragma unroll
        for (int i = 0; i < 4; i++) acc[ntl][i] = 0.f;

    // prologue: tile 0
    if (tid == 0) {
        mbar_expect_tx(sbase, A_RAW_STAGE);
        tma_load_a(tm, sbase + ARAW_OFF, kbeg, row0, zc, sbase);
    }
    spmm_load_h(Hp, HsBase, kbeg, tid);
    cp_commit();

    for (int j = 0; j < nt; j++) {
        if (j + 1 < nt) {                               // prefetch tile j+1
            int st = (j + 1) & 1;
            int k1 = kbeg + (j + 1) * BKO;
            if (tid == 0) {
                mbar_expect_tx(sbase + st * 8, A_RAW_STAGE);
                tma_load_a(tm, sbase + ARAW_OFF + st * A_RAW_STAGE, k1, row0, zc,
                           sbase + st * 8);
            }
            spmm_load_h(Hp, HsBase + st * H_STAGE_WORDS, k1, tid);
        }
        cp_commit();

        mbar_wait(sbase + (j & 1) * 8, (j >> 1) & 1);   // raw A tile j
        cp_wait1();                                     // H tile j
        __syncthreads();

        // restage: linear fp32 -> scaled fp16 padded tile (conflict-free reads)
        const float4* raw = (const float4*)(smem + ARAW_OFF + (j & 1) * A_RAW_STAGE);
#pragma unroll
        for (int i = 0; i < 12; i++) {
            int idx = tid + i * 256;        // 0..3071 float4s
            int r = idx / 48, c = idx - r * 48;
            float4 v = raw[idx];
            a16[r * A16_STRIDE + c * 2]     = pack_f16x2(v.x * ADJ_SCALE, v.y * ADJ_SCALE);
            a16[r * A16_STRIDE + c * 2 + 1] = pack_f16x2(v.z * ADJ_SCALE, v.w * ADJ_SCALE);
        }
        __syncthreads();

        const uint32_t* hs = HsBase + (j & 1) * H_STAGE_WORDS;

#pragma unroll
        for (int c = 0; c < 12; c++) {       // 12 k16-chunks per 192-col tile
            int kw  = c * 8;                 // u32 word offset in a16 row
            int kp0 = c * 8;                 // pair-row offset in hs
            uint32_t bf[4][2];
#pragma unroll
            for (int ntl = 0; ntl < 4; ntl++) {
                int col = wn + ntl * 8 + g;
                bf[ntl][0] = hs[(kp0 + t)     * HS_STRIDE + col];
                bf[ntl][1] = hs[(kp0 + t + 4) * HS_STRIDE + col];
            }
            uint32_t af[4];
            af[0] = a16[(wm + g)     * A16_STRIDE + kw + t];
            af[1] = a16[(wm + g + 8) * A16_STRIDE + kw + t];
            af[2] = a16[(wm + g)     * A16_STRIDE + kw + t + 4];
            af[3] = a16[(wm + g + 8) * A16_STRIDE + kw + t + 4];
#pragma unroll
            for (int ntl = 0; ntl < 4; ntl++)
                mma_fp16(acc[ntl], af, bf[ntl]);
        }
        __syncthreads();   // retire compute before next prefetch/restage
    }

    {
        int r_lo = row0 + wm + g;
#pragma unroll
        for (int ntl = 0; ntl < 4; ntl++) {
            int col = wn + ntl * 8 + 2 * t;
            *(float2*)&Cb[(size_t)r_lo * HID + col] =
                make_float2(acc[ntl][0] * ADJ_UNSCALE, acc[ntl][1] * ADJ_UNSCALE);
            *(float2*)&Cb[(size_t)(r_lo + 8) * HID + col] =
                make_float2(acc[ntl][2] * ADJ_UNSCALE, acc[ntl][3] * ADJ_UNSCALE);
        }
    }
}

// ---------------- fused split-K reduce + transform ---------------------------
__global__ void __launch_bounds__(256) relz_kernel(
    const float* __restrict__ part, int NB, int KS,
    const float* __restrict__ W0, const float* __restrict__ b0, int nW0,
    const float* __restrict__ W1, const float* __restrict__ b1,
    float* __restrict__ Z)
{
    int by = blockIdx.y;
    const float* Wb;
    const float* bb;
    if (by < nW0) { Wb = W0 + (size_t)by * HID * HID; bb = b0 + (size_t)by * HID; }
    else          { Wb = W1;                          bb = b1; }
    float* Zb = Z + (size_t)by * N_NODES * HID;

    __shared__ float Ws[HID * HID];
    __shared__ float xs[16][HID];

    int tx = threadIdx.x, ty = threadIdx.y;
    int tid = ty * 64 + tx;
    for (int i = tid; i < HID * HID; i += 256)
        Ws[i] = Wb[i];

    int row0 = blockIdx.x * 16;
    const size_t slab = (size_t)N_NODES * HID;
#pragma unroll
    for (int i = 0; i < 4; i++) {
        int idx = tid + i * 256;
        int r = idx >> 6, c = idx & 63;
        float v = 0.f;
        for (int s = 0; s < KS; s++)
            v += part[(size_t)(s * NB + by) * slab + (size_t)(row0 + r) * HID + c];
        xs[r][c] = v;
    }
    __syncthreads();

    float acc0 = bb[tx], acc1 = acc0, acc2 = acc0, acc3 = acc0;
    int rb = ty * 4;
#pragma unroll
    for (int k = 0; k < HID; k += 4) {
        float w0 = Ws[(k + 0) * HID + tx];
        float w1 = Ws[(k + 1) * HID + tx];
        float w2 = Ws[(k + 2) * HID + tx];
        float w3 = Ws[(k + 3) * HID + tx];
        float4 x0 = *(const float4*)&xs[rb + 0][k];
        float4 x1 = *(const float4*)&xs[rb + 1][k];
        float4 x2 = *(const float4*)&xs[rb + 2][k];
        float4 x3 = *(const float4*)&xs[rb + 3][k];
        acc0 = fmaf(x0.x, w0, fmaf(x0.y, w1, fmaf(x0.z, w2, fmaf(x0.w, w3, acc0))));
        acc1 = fmaf(x1.x, w0, fmaf(x1.y, w1, fmaf(x1.z, w2, fmaf(x1.w, w3, acc1))));
        acc2 = fmaf(x2.x, w0, fmaf(x2.y, w1, fmaf(x2.z, w2, fmaf(x2.w, w3, acc2))));
        acc3 = fmaf(x3.x, w0, fmaf(x3.y, w1, fmaf(x3.z, w2, fmaf(x3.w, w3, acc3))));
    }
    Zb[(size_t)(row0 + rb + 0) * HID + tx] = tanhf(acc0);
    Zb[(size_t)(row0 + rb + 1) * HID + tx] = tanhf(acc1);
    Zb[(size_t)(row0 + rb + 2) * HID + tx] = tanhf(acc2);
    Zb[(size_t)(row0 + rb + 3) * HID + tx] = tanhf(acc3);
}

// ---------------- attention pooling: 4 nodes/block ---------------------------
__global__ void __launch_bounds__(256) attn_kernel(
    const float* __restrict__ Z, const float* __restrict__ aW,
    const float* __restrict__ ab, const float* __restrict__ aq,
    float* __restrict__ outF, __half* __restrict__ outP, int K)
{
    __shared__ float saW[HID * ATT_H];
    __shared__ float zs[4][3 * HID];
    __shared__ float prt[4][2][3];

    int tid = threadIdx.x;
    int n0 = blockIdx.x * 4;

    for (int i = tid; i < HID * ATT_H; i += 256) saW[i] = aW[i];
    for (int i = tid; i < 4 * K * HID; i += 256) {
        int node = i / (K * HID);
        int rem  = i - node * K * HID;
        int k = rem >> 6, d = rem & 63;
        zs[node][k * HID + d] = Z[((size_t)k * N_NODES + n0 + node) * HID + d];
    }
    __syncthreads();

    int w = tid >> 5, lane = tid & 31;
    int node = w >> 1, half = w & 1;
    int c0 = half * 64 + lane;

    float ab0 = ab[c0], ab1 = ab[c0 + 32];
    float q0  = aq[c0], q1  = aq[c0 + 32];
    for (int k = 0; k < K; k++) {
        const float* zr = &zs[node][k * HID];
        float u0 = ab0, u1 = ab1;
#pragma unroll 8
        for (int d = 0; d < HID; d++) {
            float zv = zr[d];
            u0 = fmaf(zv, saW[d * ATT_H + c0], u0);
            u1 = fmaf(zv, saW[d * ATT_H + c0 + 32], u1);
        }
        float p = tanha(u0) * q0 + tanha(u1) * q1;
#pragma unroll
        for (int m = 16; m >= 1; m >>= 1)
            p += __shfl_xor_sync(0xffffffffu, p, m);
        if (lane == 0) prt[node][half][k] = p;
    }
    __syncthreads();

    float sc[3], mx = -1e30f;
    for (int k = 0; k < K; k++) {
        sc[k] = prt[node][0][k] + prt[node][1][k];
        mx = fmaxf(mx, sc[k]);
    }
    float e[3], den = 0.f;
    for (int k = 0; k < K; k++) { e[k] = expf(sc[k] - mx); den += e[k]; }

    int col = half * 32 + lane;
    float o = 0.f;
    for (int k = 0; k < K; k++)
        o += (e[k] / den) * zs[node][k * HID + col];
    int n = n0 + node;
    if (outF) outF[(size_t)n * HID + col] = o;
    if (outP) outP[((size_t)(n >> 1) * HID + col) * 2 + (n & 1)] = __float2half_rn(o);
}

// ---------------- fused final: attention over 2 + projection -----------------
__global__ void __launch_bounds__(256) final_kernel(
    const float* __restrict__ Hrel, const float* __restrict__ Hii,
    const float* __restrict__ aW, const float* __restrict__ ab,
    const float* __restrict__ aq, const float* __restrict__ Wout,
    const float* __restrict__ bout, float* __restrict__ out, int out_total)
{
    extern __shared__ float sm[];
    float* saW = sm;
    float* sWo = saW + 8192;
    float* sz  = sWo + 2048;
    float* spl = sz + 2048;
    float* sab = spl + 1024;
    float* sq  = sab + 128;
    float* sbo = sq + 128;
    float* ss  = sbo + 32;

    int tid = threadIdx.x;
    for (int i = tid; i < 8192; i += 256) saW[i] = aW[i];
    for (int i = tid; i < 2048; i += 256) sWo[i] = Wout[i];
    if (tid < 128) { sab[tid] = ab[tid]; sq[tid] = aq[tid]; }
    if (tid < 32)  sbo[tid] = bout[tid];

    int row0 = blockIdx.x * 16;
#pragma unroll
    for (int i = 0; i < 8; i++) {
        int idx = tid + i * 256;
        int k = idx >> 10, rem = idx & 1023;
        int rr = rem >> 6, c = rem & 63;
        const float* src = k ? Hii : Hrel;
        sz[k * 1024 + rr * 64 + c] = src[(size_t)(row0 + rr) * HID + c];
    }
    __syncthreads();

    {
        int row = tid >> 4, seg = tid & 15, j0 = seg * 8;
        for (int r = 0; r < 2; r++) {
            const float* zr = sz + r * 1024 + row * 64;
            float u[8];
#pragma unroll
            for (int jj = 0; jj < 8; jj++) u[jj] = sab[j0 + jj];
#pragma unroll 4
            for (int d = 0; d < 64; d++) {
                float zv = zr[d];
                float4 wA = *(const float4*)&saW[d * 128 + j0];
                float4 wB = *(const float4*)&saW[d * 128 + j0 + 4];
                u[0] = fmaf(zv, wA.x, u[0]); u[1] = fmaf(zv, wA.y, u[1]);
                u[2] = fmaf(zv, wA.z, u[2]); u[3] = fmaf(zv, wA.w, u[3]);
                u[4] = fmaf(zv, wB.x, u[4]); u[5] = fmaf(zv, wB.y, u[5]);
                u[6] = fmaf(zv, wB.z, u[6]); u[7] = fmaf(zv, wB.w, u[7]);
            }
            float partial = 0.f;
#pragma unroll
            for (int jj = 0; jj < 8; jj++)
                partial += tanha(u[jj]) * sq[j0 + jj];
#pragma unroll
            for (int m = 8; m >= 1; m >>= 1)
                partial += __shfl_xor_sync(0xffffffffu, partial, m);
            if (seg == 0) ss[row * 4 + r] = partial;
        }
    }
    __syncthreads();

    {
        int tx = tid & 63, qy = tid >> 6;
#pragma unroll
        for (int i = 0; i < 4; i++) {
            int rr = qy * 4 + i;
            float s0 = ss[rr * 4 + 0], s1 = ss[rr * 4 + 1];
            float mx = fmaxf(s0, s1);
            float e0 = expf(s0 - mx), e1 = expf(s1 - mx);
            float den = e0 + e1;
            float o = (e0 / den) * sz[rr * 64 + tx] + (e1 / den) * sz[1024 + rr * 64 + tx];
            spl[rr * 64 + tx] = o;
            if (out_total > N_NODES * OUT_DIM)
                out[(size_t)N_NODES * OUT_DIM + (size_t)(row0 + rr) * HID + tx] = o;
        }
    }
    __syncthreads();

    {
        int row = tid >> 4;
        int c0 = tid & 15;
        const float* pr = spl + row * 64;
        float acc0 = sbo[c0], acc1 = sbo[c0 + 16];
#pragma unroll
        for (int d = 0; d < 64; d++) {
            float pv = pr[d];
            acc0 = fmaf(pv, sWo[d * 32 + c0], acc0);
            acc1 = fmaf(pv, sWo[d * 32 + c0 + 16], acc1);
        }
        out[(size_t)(row0 + row) * OUT_DIM + c0]      = acc0;
        out[(size_t)(row0 + row) * OUT_DIM + c0 + 16] = acc1;
    }
}

// ---------------- host: tensor map creation ----------------------------------
typedef CUresult (*EncodeTiledFn)(
    CUtensorMap*, CUtensorMapDataType, cuuint32_t, void*,
    const cuuint64_t*, const cuuint64_t*, const cuuint32_t*, const cuuint32_t*,
    CUtensorMapInterleave, CUtensorMapSwizzle, CUtensorMapL2promotion,
    CUtensorMapFloatOOBfill);

static void make_adj_map(EncodeTiledFn enc, CUtensorMap* tm, const void* base, int nb)
{
    cuuint64_t dims[3]    = { N_NODES, N_NODES, (cuuint64_t)nb };
    cuuint64_t strides[2] = { (cuuint64_t)N_NODES * 4,
                              (cuuint64_t)N_NODES * N_NODES * 4 };
    cuuint32_t box[3]     = { BKO, BM, 1 };
    cuuint32_t estr[3]    = { 1, 1, 1 };
    enc(tm, CU_TENSOR_MAP_DATA_TYPE_FLOAT32, 3, (void*)base,
        dims, strides, box, estr,
        CU_TENSOR_MAP_INTERLEAVE_NONE, CU_TENSOR_MAP_SWIZZLE_NONE,
        CU_TENSOR_MAP_L2_PROMOTION_L2_256B, CU_TENSOR_MAP_FLOAT_OOB_FILL_NONE);
}

// ---------------- launch ----------------------------------------------------
extern "C" void kernel_launch(void* const* d_in, const int* in_sizes, int n_in,
                              void* d_out, int out_size)
{
    const float* feat_item = (const float*)d_in[0];
    const float* feat_user = (const float*)d_in[1];
    const float* adj_ii    = (const float*)d_in[2];
    const float* adj_mp    = (const float*)d_in[3];
    const float* adj_ui    = (const float*)d_in[4];
    const float* W_map0 = (const float*)d_in[5];
    const float* b_map0 = (const float*)d_in[6];
    const float* W_map1 = (const float*)d_in[7];
    const float* b_map1 = (const float*)d_in[8];
    const float* W_rel  = (const float*)d_in[9];
    const float* b_rel  = (const float*)d_in[10];
    const float* rel_aW = (const float*)d_in[11];
    const float* rel_ab = (const float*)d_in[12];
    const float* rel_aq = (const float*)d_in[13];
    const float* W_sch  = (const float*)d_in[14];
    const float* b_sch  = (const float*)d_in[15];
    const float* sch_aW = (const float*)d_in[16];
    const float* sch_ab = (const float*)d_in[17];
    const float* sch_aq = (const float*)d_in[18];
    const float* W_ii   = (const float*)d_in[19];
    const float* b_ii   = (const float*)d_in[20];
    const float* ii_aW  = (const float*)d_in[21];
    const float* ii_ab  = (const float*)d_in[22];
    const float* ii_aq  = (const float*)d_in[23];
    const float* fin_aW = (const float*)d_in[24];
    const float* fin_ab = (const float*)d_in[25];
    const float* fin_aq = (const float*)d_in[26];
    const float* W_out  = (const float*)d_in[27];
    const float* b_out  = (const float*)d_in[28];

    float *partb, *zbuf, *zii, *relagg, *itemitem;
    uint32_t *h0p, *h1p, *ictp;
    cudaGetSymbolAddress((void**)&h0p, g_h0p);
    cudaGetSymbolAddress((void**)&h1p, g_h1p);
    cudaGetSymbolAddress((void**)&ictp, g_ictp);
    cudaGetSymbolAddress((void**)&partb, g_part);
    cudaGetSymbolAddress((void**)&zbuf, g_z);
    cudaGetSymbolAddress((void**)&zii, g_zii);
    cudaGetSymbolAddress((void**)&relagg,   g_relagg);
    cudaGetSymbolAddress((void**)&itemitem, g_itemitem);

    EncodeTiledFn enc = nullptr;
    {
        void* fp = nullptr;
        cudaDriverEntryPointQueryResult qr;
        cudaGetDriverEntryPoint("cuTensorMapEncodeTiled", &fp,
                                cudaEnableDefault, &qr);
        enc = (EncodeTiledFn)fp;
    }
    CUtensorMap tm_mp, tm_ui, tm_ii;
    make_adj_map(enc, &tm_mp, adj_mp, 3);
    make_adj_map(enc, &tm_ui, adj_ui, 2);
    make_adj_map(enc, &tm_ii, adj_ii, 2);

    cudaFuncSetAttribute(spmm_kernel,
                         cudaFuncAttributeMaxDynamicSharedMemorySize, SPMM_SMEM_BYTES);
    const int FIN_SMEM = (8192 + 2048 + 2048 + 1024 + 128 + 128 + 32 + 64) * 4;
    cudaFuncSetAttribute(final_kernel,
                         cudaFuncAttributeMaxDynamicSharedMemorySize, FIN_SMEM);

    dim3 blk64x4(64, 4);

    // Stage 1: feature mapping (fused pack)
    map_kernel<<<N_NODES / 4, blk64x4>>>(feat_item, W_map0, b_map0, h0p);
    map_kernel<<<N_NODES / 4, blk64x4>>>(feat_user, W_map1, b_map1, h1p);

    // Stage 2: phase-A GEMMs (3x adj_mp@h0 + 2x adj_ui@h1), split-K=2 (3072=16 tiles)
    spmm_kernel<<<dim3(N_NODES / BM, 5, 2), 256, SPMM_SMEM_BYTES>>>(
        tm_mp, tm_ui, 3, h0p, h1p, partb, N_NODES / 2);

    // Stage 3: 5-batch reduce+transform, then attention pooling
    relz_kernel<<<dim3(N_NODES / 16, 5), blk64x4>>>(
        partb, 5, 2, W_rel, b_rel, 3, W_sch, b_sch, zbuf);
    attn_kernel<<<N_NODES / 4, 256>>>(zbuf, rel_aW, rel_ab, rel_aq,
                                      relagg, nullptr, 3);
    attn_kernel<<<N_NODES / 4, 256>>>(zbuf + 3 * N_NODES * HID,
                                      sch_aW, sch_ab, sch_aq,
                                      nullptr, (__half*)ictp, 2);

    // Stage 4: phase-B GEMMs (2x adj_ii@itemcls), split-K=4 (1536=8 tiles)
    spmm_kernel<<<dim3(N_NODES / BM, 2, 4), 256, SPMM_SMEM_BYTES>>>(
        tm_ii, tm_ii, 2, ictp, ictp, partb, N_NODES / 4);

    // Stage 5: reduce+transform + attention (item-item)
    relz_kernel<<<dim3(N_NODES / 16, 2), blk64x4>>>(
        partb, 2, 4, W_ii, b_ii, 2, W_ii, b_ii, zii);
    attn_kernel<<<N_NODES / 4, 256>>>(zii, ii_aW, ii_ab, ii_aq,
                                      itemitem, nullptr, 2);

    // Stage 6: fused final attention + projection
    final_kernel<<<N_NODES / 16, 256, FIN_SMEM>>>(
        relagg, itemitem, fin_aW, fin_ab, fin_aq,
        W_out, b_out, (float*)d_out, out_size);
}

// round 16
// speedup vs baseline: 1.1388x; 1.1388x over previous
#include <cuda_runtime.h>
#include <cuda.h>
#include <cuda_fp16.h>
#include <math.h>
#include <stdint.h>

#define N_NODES 6144
#define D_IN    256
#define HID     64
#define OUT_DIM 32
#define ATT_H   128

#define ADJ_SCALE   2048.0f
#define ADJ_UNSCALE 4.8828125e-4f   // 1/2048

// ---------------- scratch (device globals; no allocation allowed) ----------
__device__ uint32_t g_h0p[N_NODES * HID / 2];
__device__ uint32_t g_h1p[N_NODES * HID / 2];
__device__ uint32_t g_ictp[N_NODES * HID / 2];
__device__ float g_part[15 * N_NODES * HID];
__device__ float g_z3[3 * N_NODES * HID];
__device__ float g_z2[2 * N_NODES * HID];
__device__ float g_zii[2 * N_NODES * HID];
__device__ float g_relagg  [N_NODES * HID];
__device__ float g_itemitem[N_NODES * HID];

// ---------------- helpers -----------------------------------------------------
__device__ __forceinline__ uint32_t smem_u32(const void* p) {
    uint32_t a;
    asm("{ .reg .u64 t; cvta.to.shared.u64 t, %1; cvt.u32.u64 %0, t; }"
        : "=r"(a) : "l"(p));
    return a;
}
__device__ __forceinline__ uint32_t pack_f16x2(float lo, float hi) {
    uint32_t r;
    asm("cvt.rn.f16x2.f32 %0, %1, %2;" : "=r"(r) : "f"(hi), "f"(lo));
    return r;
}
__device__ __forceinline__ uint32_t ld_scale_pack(const float* p) {
    float2 v = *(const float2*)p;
    return pack_f16x2(v.x * ADJ_SCALE, v.y * ADJ_SCALE);
}
__device__ __forceinline__ void mma_fp16(float* c, const uint32_t* a, const uint32_t* b) {
    asm("mma.sync.aligned.m16n8k16.row.col.f32.f16.f16.f32 "
        "{%0,%1,%2,%3}, {%4,%5,%6,%7}, {%8,%9}, {%0,%1,%2,%3};"
        : "+f"(c[0]), "+f"(c[1]), "+f"(c[2]), "+f"(c[3])
        : "r"(a[0]), "r"(a[1]), "r"(a[2]), "r"(a[3]),
          "r"(b[1] * 0 + b[0]), "r"(b[1]));
}
__device__ __forceinline__ void cp16(void* dst, const void* src) {
    uint32_t d = (uint32_t)__cvta_generic_to_shared(dst);
    asm volatile("cp.async.cg.shared.global [%0], [%1], 16;" :: "r"(d), "l"(src));
}
__device__ __forceinline__ void cp_commit() {
    asm volatile("cp.async.commit_group;" ::: "memory");
}
__device__ __forceinline__ void cp_wait1() {
    asm volatile("cp.async.wait_group 1;" ::: "memory");
}
__device__ __forceinline__ void mbar_init(uint32_t addr, uint32_t cnt) {
    asm volatile("mbarrier.init.shared.b64 [%0], %1;" :: "r"(addr), "r"(cnt) : "memory");
}
__device__ __forceinline__ void mbar_expect_tx(uint32_t addr, uint32_t bytes) {
    asm volatile("mbarrier.arrive.expect_tx.shared.b64 _, [%0], %1;"
                 :: "r"(addr), "r"(bytes) : "memory");
}
__device__ __forceinline__ void mbar_wait(uint32_t addr, uint32_t parity) {
    uint32_t done;
    asm volatile(
        "{ .reg .pred p; mbarrier.try_wait.parity.acquire.cta.shared::cta.b64 p, [%1], %2;"
        " selp.b32 %0, 1, 0, p; }"
        : "=r"(done) : "r"(addr), "r"(parity) : "memory");
    if (!done) {
        asm volatile(
            "{ .reg .pred P1;\n"
            "WL_%=: mbarrier.try_wait.parity.acquire.cta.shared::cta.b64 P1, [%0], %1, 0x989680;\n"
            "@P1 bra.uni WD_%=;\n"
            "bra.uni WL_%=;\n"
            "WD_%=: }"
            :: "r"(addr), "r"(parity) : "memory");
    }
}
__device__ __forceinline__ void tma_load_a(
    const CUtensorMap* tm, uint32_t dst, int x, int y, int z, uint32_t mbar)
{
    asm volatile(
        "cp.async.bulk.tensor.3d.shared::cta.global.tile.mbarrier::complete_tx::bytes "
        "[%0], [%1, {%2, %3, %4}], [%5];"
        :: "r"(dst), "l"(tm), "r"(x), "r"(y), "r"(z), "r"(mbar)
        : "memory");
}

// ---------------- feature mapping + fp16 pack --------------------------------
__global__ void __launch_bounds__(256) map_kernel(
    const float* __restrict__ feat, const float* __restrict__ W,
    const float* __restrict__ b, uint32_t* __restrict__ outp)
{
    __shared__ float hs[4][HID];
    int tx = threadIdx.x, ty = threadIdx.y;
    int row = blockIdx.x * 4 + ty;
    const float* fr = feat + (size_t)row * D_IN;
    float acc = b[tx];
#pragma unroll 8
    for (int k = 0; k < D_IN; k++)
        acc = fmaf(fr[k], W[k * HID + tx], acc);
    hs[ty][tx] = tanhf(acc);
    __syncthreads();
    int tid = ty * 64 + tx;
    if (tid < 128) {
        int pr = tid >> 6, c = tid & 63;
        outp[(size_t)(blockIdx.x * 2 + pr) * HID + c] =
            pack_f16x2(hs[2 * pr][c], hs[2 * pr + 1][c]);
    }
}

// ---------------- big GEMM: wide K-tiles (2x TMA boxes), 2 CTA/SM ------------
// BM=128, BKO=64 (2 sub-tiles of 32), BN=64. 256 threads, 8 warps (4Mx2N).
#define BM 128
#define BK 32
#define NSUB 2
#define BKO (BK * NSUB)
#define HS_STRIDE 72
#define STAGES 2
#define A_SUB_BYTES (BM * 128)
#define A_TILE_BYTES (NSUB * A_SUB_BYTES)          // 32 KB
#define H_STAGE_WORDS (NSUB * 16 * HS_STRIDE)
#define H_STAGE_BYTES (H_STAGE_WORDS * 4)          // 9216 B
#define A_OFF 1024
#define H_OFF (A_OFF + STAGES * A_TILE_BYTES)
#define SPMM_SMEM_BYTES (H_OFF + STAGES * H_STAGE_BYTES)   // ~84 KB

__device__ __forceinline__ void spmm_load_h(
    const uint32_t* __restrict__ Hp, uint32_t* hs, int k0, int tid)
{
#pragma unroll
    for (int i = 0; i < 2; i++) {
        int idx = tid + i * 256;           // 0..511
        int r   = idx >> 4;                // pair-row 0..31
        int c4  = (idx & 15) << 2;
        cp16(hs + r * HS_STRIDE + c4, Hp + (size_t)((k0 >> 1) + r) * HID + c4);
    }
}

__global__ void __launch_bounds__(256, 2) spmm_kernel(
    const __grid_constant__ CUtensorMap tmA,
    const __grid_constant__ CUtensorMap tmB,
    int nA, const uint32_t* __restrict__ hA, const uint32_t* __restrict__ hB,
    float* __restrict__ part, int kPerSplit)
{
    extern __shared__ __align__(1024) char smem[];
    uint32_t sbase = smem_u32(smem);

    int b = blockIdx.y;
    const CUtensorMap* tm;
    const uint32_t* Hp;
    int zc;
    if (b < nA) { tm = &tmA; zc = b;      Hp = hA; }
    else        { tm = &tmB; zc = b - nA; Hp = hB; }

    float* Cb = part + ((size_t)blockIdx.z * gridDim.y + b) * (size_t)(N_NODES * HID);
    uint32_t* HsBase = (uint32_t*)(smem + H_OFF);

    int tid  = threadIdx.x;
    int lane = tid & 31;
    int warp = tid >> 5;
    int g = lane >> 2;
    int t = lane & 3;
    int wm = (warp & 3) * 32;
    int wn = (warp >> 2) * 32;
    int row0 = blockIdx.x * BM;
    int kbeg = blockIdx.z * kPerSplit;
    int nt = kPerSplit / BKO;

    if (tid == 0)
        for (int s = 0; s < STAGES; s++)
            mbar_init(sbase + s * 8, 1);
    __syncthreads();

    float acc[2][4][4];
#pragma unroll
    for (int mt = 0; mt < 2; mt++)
#pragma unroll
        for (int ntl = 0; ntl < 4; ntl++)
#pragma unroll
            for (int i = 0; i < 4; i++) acc[mt][ntl][i] = 0.f;

    if (tid == 0) {
        mbar_expect_tx(sbase, A_TILE_BYTES);
#pragma unroll
        for (int s = 0; s < NSUB; s++)
            tma_load_a(tm, sbase + A_OFF + s * A_SUB_BYTES,
                       kbeg + s * BK, row0, zc, sbase);
    }
    spmm_load_h(Hp, HsBase, kbeg, tid);
    cp_commit();

    for (int j = 0; j < nt; j++) {
        if (j + 1 < nt) {
            int st = (j + 1) & 1;
            int k1 = kbeg + (j + 1) * BKO;
            if (tid == 0) {
                mbar_expect_tx(sbase + st * 8, A_TILE_BYTES);
#pragma unroll
                for (int s = 0; s < NSUB; s++)
                    tma_load_a(tm, sbase + A_OFF + st * A_TILE_BYTES + s * A_SUB_BYTES,
                               k1 + s * BK, row0, zc, sbase + st * 8);
            }
            spmm_load_h(Hp, HsBase + st * H_STAGE_WORDS, k1, tid);
        }
        cp_commit();

        mbar_wait(sbase + (j & 1) * 8, (j >> 1) & 1);
        cp_wait1();
        __syncthreads();

        const char*     aStage = smem + A_OFF + (j & 1) * A_TILE_BYTES;
        const uint32_t* hStage = HsBase + (j & 1) * H_STAGE_WORDS;

#pragma unroll
        for (int sub = 0; sub < NSUB; sub++) {
            const char*     as = aStage + sub * A_SUB_BYTES;
            const uint32_t* hs = hStage + sub * 16 * HS_STRIDE;
#pragma unroll
            for (int c = 0; c < 2; c++) {
                int kk  = c * 16;
                int kp0 = c * 8;
                uint32_t bf[4][2];
#pragma unroll
                for (int ntl = 0; ntl < 4; ntl++) {
                    int col = wn + ntl * 8 + g;
                    bf[ntl][0] = hs[(kp0 + t)     * HS_STRIDE + col];
                    bf[ntl][1] = hs[(kp0 + t + 4) * HS_STRIDE + col];
                }
#pragma unroll
                for (int mt = 0; mt < 2; mt++) {
                    int r0l = wm + mt * 16 + g;
                    int r1l = r0l + 8;
                    uint32_t m0 = (uint32_t)(r0l & 7) << 4;
                    uint32_t m1 = (uint32_t)(r1l & 7) << 4;
                    uint32_t base0 = (uint32_t)(r0l * 128 + (kk + 2 * t) * 4);
                    uint32_t base1 = (uint32_t)(r1l * 128 + (kk + 2 * t) * 4);
                    uint32_t af[4];
                    af[0] = ld_scale_pack((const float*)(as + (base0 ^ m0)));
                    af[1] = ld_scale_pack((const float*)(as + (base1 ^ m1)));
                    af[2] = ld_scale_pack((const float*)(as + ((base0 + 32) ^ m0)));
                    af[3] = ld_scale_pack((const float*)(as + ((base1 + 32) ^ m1)));
#pragma unroll
                    for (int ntl = 0; ntl < 4; ntl++)
                        mma_fp16(acc[mt][ntl], af, bf[ntl]);
                }
            }
        }
        __syncthreads();
    }

#pragma unroll
    for (int mt = 0; mt < 2; mt++) {
        int r_lo = row0 + wm + mt * 16 + g;
#pragma unroll
        for (int ntl = 0; ntl < 4; ntl++) {
            int col = wn + ntl * 8 + 2 * t;
            *(float2*)&Cb[(size_t)r_lo * HID + col] =
                make_float2(acc[mt][ntl][0] * ADJ_UNSCALE,
                            acc[mt][ntl][1] * ADJ_UNSCALE);
            *(float2*)&Cb[(size_t)(r_lo + 8) * HID + col] =
                make_float2(acc[mt][ntl][2] * ADJ_UNSCALE,
                            acc[mt][ntl][3] * ADJ_UNSCALE);
        }
    }
}

// ---------------- fused split-K reduce + transform (R13 version) -------------
__global__ void __launch_bounds__(256) relz_kernel(
    const float* __restrict__ part, int NB, int KS, int batch0,
    const float* __restrict__ W, const float* __restrict__ bias,
    float* __restrict__ Z, int wStride, int bStride)
{
    int batch = batch0 + blockIdx.y;
    const float* Wb = W + (size_t)blockIdx.y * wStride;
    const float* bb = bias + (size_t)blockIdx.y * bStride;
    float* Zb = Z + (size_t)blockIdx.y * N_NODES * HID;

    __shared__ float Ws[HID * HID];
    __shared__ float xs[16][HID];

    int tx = threadIdx.x, ty = threadIdx.y;
    int tid = ty * 64 + tx;
    for (int i = tid; i < HID * HID; i += 256)
        Ws[i] = Wb[i];

    int row0 = blockIdx.x * 16;
    const size_t slab = (size_t)N_NODES * HID;
#pragma unroll
    for (int i = 0; i < 4; i++) {
        int idx = tid + i * 256;
        int r = idx >> 6, c = idx & 63;
        float v = 0.f;
        for (int s = 0; s < KS; s++)
            v += part[(size_t)(s * NB + batch) * slab + (size_t)(row0 + r) * HID + c];
        xs[r][c] = v;
    }
    __syncthreads();

    float acc0 = bb[tx], acc1 = acc0, acc2 = acc0, acc3 = acc0;
    int rb = ty * 4;
#pragma unroll
    for (int k = 0; k < HID; k += 4) {
        float w0 = Ws[(k + 0) * HID + tx];
        float w1 = Ws[(k + 1) * HID + tx];
        float w2 = Ws[(k + 2) * HID + tx];
        float w3 = Ws[(k + 3) * HID + tx];
        float4 x0 = *(const float4*)&xs[rb + 0][k];
        float4 x1 = *(const float4*)&xs[rb + 1][k];
        float4 x2 = *(const float4*)&xs[rb + 2][k];
        float4 x3 = *(const float4*)&xs[rb + 3][k];
        acc0 = fmaf(x0.x, w0, fmaf(x0.y, w1, fmaf(x0.z, w2, fmaf(x0.w, w3, acc0))));
        acc1 = fmaf(x1.x, w0, fmaf(x1.y, w1, fmaf(x1.z, w2, fmaf(x1.w, w3, acc1))));
        acc2 = fmaf(x2.x, w0, fmaf(x2.y, w1, fmaf(x2.z, w2, fmaf(x2.w, w3, acc2))));
        acc3 = fmaf(x3.x, w0, fmaf(x3.y, w1, fmaf(x3.z, w2, fmaf(x3.w, w3, acc3))));
    }
    Zb[(size_t)(row0 + rb + 0) * HID + tx] = tanhf(acc0);
    Zb[(size_t)(row0 + rb + 1) * HID + tx] = tanhf(acc1);
    Zb[(size_t)(row0 + rb + 2) * HID + tx] = tanhf(acc2);
    Zb[(size_t)(row0 + rb + 3) * HID + tx] = tanhf(acc3);
}

// ---------------- attention pooling over K slots (R13 version) ---------------
__global__ void __launch_bounds__(128) attn_kernel(
    const float* __restrict__ Z, const float* __restrict__ aW,
    const float* __restrict__ ab, const float* __restrict__ aq,
    float* __restrict__ outF, __half* __restrict__ outP, int K)
{
    int n = blockIdx.x;
    int j = threadIdx.x;
    __shared__ float zs[4 * HID];
    __shared__ float red[ATT_H];
    __shared__ float sc[4];

    for (int k = 0; k < K; k++)
        if (j < HID) zs[k * HID + j] = Z[((size_t)k * N_NODES + n) * HID + j];
    __syncthreads();

    for (int k = 0; k < K; k++) {
        float u = ab[j];
#pragma unroll
        for (int d = 0; d < HID; d++)
            u = fmaf(zs[k * HID + d], aW[d * ATT_H + j], u);
        red[j] = tanhf(u) * aq[j];
        __syncthreads();
#pragma unroll
        for (int off = 64; off >= 1; off >>= 1) {
            if (j < off) red[j] += red[j + off];
            __syncthreads();
        }
        if (j == 0) sc[k] = red[0];
        __syncthreads();
    }

    float mx = -1e30f;
    for (int k = 0; k < K; k++) mx = fmaxf(mx, sc[k]);
    float e[4]; float den = 0.f;
    for (int k = 0; k < K; k++) { e[k] = expf(sc[k] - mx); den += e[k]; }

    if (j < HID) {
        float o = 0.f;
        for (int k = 0; k < K; k++) o += (e[k] / den) * zs[k * HID + j];
        if (outF) outF[(size_t)n * HID + j] = o;
        if (outP) outP[((size_t)(n >> 1) * HID + j) * 2 + (n & 1)] = __float2half_rn(o);
    }
}

// ---------------- fused final: attention over 2 + projection (R13) -----------
__global__ void __launch_bounds__(256) final_kernel(
    const float* __restrict__ Hrel, const float* __restrict__ Hii,
    const float* __restrict__ aW, const float* __restrict__ ab,
    const float* __restrict__ aq, const float* __restrict__ Wout,
    const float* __restrict__ bout, float* __restrict__ out, int out_total)
{
    extern __shared__ float sm[];
    float* saW = sm;
    float* sWo = saW + 8192;
    float* sz  = sWo + 2048;
    float* spl = sz + 2048;
    float* sab = spl + 1024;
    float* sq  = sab + 128;
    float* sbo = sq + 128;
    float* ss  = sbo + 32;

    int tid = threadIdx.x;
    for (int i = tid; i < 8192; i += 256) saW[i] = aW[i];
    for (int i = tid; i < 2048; i += 256) sWo[i] = Wout[i];
    if (tid < 128) { sab[tid] = ab[tid]; sq[tid] = aq[tid]; }
    if (tid < 32)  sbo[tid] = bout[tid];

    int row0 = blockIdx.x * 16;
#pragma unroll
    for (int i = 0; i < 8; i++) {
        int idx = tid + i * 256;
        int k = idx >> 10, rem = idx & 1023;
        int rr = rem >> 6, c = rem & 63;
        const float* src = k ? Hii : Hrel;
        sz[k * 1024 + rr * 64 + c] = src[(size_t)(row0 + rr) * HID + c];
    }
    __syncthreads();

    {
        int row = tid >> 4, seg = tid & 15, j0 = seg * 8;
        for (int r = 0; r < 2; r++) {
            const float* zr = sz + r * 1024 + row * 64;
            float u[8];
#pragma unroll
            for (int jj = 0; jj < 8; jj++) u[jj] = sab[j0 + jj];
#pragma unroll 4
            for (int d = 0; d < 64; d++) {
                float zv = zr[d];
                float4 wA = *(const float4*)&saW[d * 128 + j0];
                float4 wB = *(const float4*)&saW[d * 128 + j0 + 4];
                u[0] = fmaf(zv, wA.x, u[0]); u[1] = fmaf(zv, wA.y, u[1]);
                u[2] = fmaf(zv, wA.z, u[2]); u[3] = fmaf(zv, wA.w, u[3]);
                u[4] = fmaf(zv, wB.x, u[4]); u[5] = fmaf(zv, wB.y, u[5]);
                u[6] = fmaf(zv, wB.z, u[6]); u[7] = fmaf(zv, wB.w, u[7]);
            }
            float partial = 0.f;
#pragma unroll
            for (int jj = 0; jj < 8; jj++)
                partial += tanhf(u[jj]) * sq[j0 + jj];
#pragma unroll
            for (int m = 8; m >= 1; m >>= 1)
                partial += __shfl_xor_sync(0xffffffffu, partial, m);
            if (seg == 0) ss[row * 4 + r] = partial;
        }
    }
    __syncthreads();

    {
        int tx = tid & 63, qy = tid >> 6;
#pragma unroll
        for (int i = 0; i < 4; i++) {
            int rr = qy * 4 + i;
            float s0 = ss[rr * 4 + 0], s1 = ss[rr * 4 + 1];
            float mx = fmaxf(s0, s1);
            float e0 = expf(s0 - mx), e1 = expf(s1 - mx);
            float den = e0 + e1;
            float o = (e0 / den) * sz[rr * 64 + tx] + (e1 / den) * sz[1024 + rr * 64 + tx];
            spl[rr * 64 + tx] = o;
            if (out_total > N_NODES * OUT_DIM)
                out[(size_t)N_NODES * OUT_DIM + (size_t)(row0 + rr) * HID + tx] = o;
        }
    }
    __syncthreads();

    {
        int row = tid >> 4;
        int c0 = tid & 15;
        const float* pr = spl + row * 64;
        float acc0 = sbo[c0], acc1 = sbo[c0 + 16];
#pragma unroll
        for (int d = 0; d < 64; d++) {
            float pv = pr[d];
            acc0 = fmaf(pv, sWo[d * 32 + c0], acc0);
            acc1 = fmaf(pv, sWo[d * 32 + c0 + 16], acc1);
        }
        out[(size_t)(row0 + row) * OUT_DIM + c0]      = acc0;
        out[(size_t)(row0 + row) * OUT_DIM + c0 + 16] = acc1;
    }
}

// ---------------- host: tensor map creation ----------------------------------
typedef CUresult (*EncodeTiledFn)(
    CUtensorMap*, CUtensorMapDataType, cuuint32_t, void*,
    const cuuint64_t*, const cuuint64_t*, const cuuint32_t*, const cuuint32_t*,
    CUtensorMapInterleave, CUtensorMapSwizzle, CUtensorMapL2promotion,
    CUtensorMapFloatOOBfill);

static void make_adj_map(EncodeTiledFn enc, CUtensorMap* tm, const void* base, int nb)
{
    cuuint64_t dims[3]    = { N_NODES, N_NODES, (cuuint64_t)nb };
    cuuint64_t strides[2] = { (cuuint64_t)N_NODES * 4,
                              (cuuint64_t)N_NODES * N_NODES * 4 };
    cuuint32_t box[3]     = { BK, BM, 1 };
    cuuint32_t estr[3]    = { 1, 1, 1 };
    enc(tm, CU_TENSOR_MAP_DATA_TYPE_FLOAT32, 3, (void*)base,
        dims, strides, box, estr,
        CU_TENSOR_MAP_INTERLEAVE_NONE, CU_TENSOR_MAP_SWIZZLE_128B,
        CU_TENSOR_MAP_L2_PROMOTION_L2_256B, CU_TENSOR_MAP_FLOAT_OOB_FILL_NONE);
}

// ---------------- launch ----------------------------------------------------
extern "C" void kernel_launch(void* const* d_in, const int* in_sizes, int n_in,
                              void* d_out, int out_size)
{
    const float* feat_item = (const float*)d_in[0];
    const float* feat_user = (const float*)d_in[1];
    const float* adj_ii    = (const float*)d_in[2];
    const float* adj_mp    = (const float*)d_in[3];
    const float* adj_ui    = (const float*)d_in[4];
    const float* W_map0 = (const float*)d_in[5];
    const float* b_map0 = (const float*)d_in[6];
    const float* W_map1 = (const float*)d_in[7];
    const float* b_map1 = (const float*)d_in[8];
    const float* W_rel  = (const float*)d_in[9];
    const float* b_rel  = (const float*)d_in[10];
    const float* rel_aW = (const float*)d_in[11];
    const float* rel_ab = (const float*)d_in[12];
    const float* rel_aq = (const float*)d_in[13];
    const float* W_sch  = (const float*)d_in[14];
    const float* b_sch  = (const float*)d_in[15];
    const float* sch_aW = (const float*)d_in[16];
    const float* sch_ab = (const float*)d_in[17];
    const float* sch_aq = (const float*)d_in[18];
    const float* W_ii   = (const float*)d_in[19];
    const float* b_ii   = (const float*)d_in[20];
    const float* ii_aW  = (const float*)d_in[21];
    const float* ii_ab  = (const float*)d_in[22];
    const float* ii_aq  = (const float*)d_in[23];
    const float* fin_aW = (const float*)d_in[24];
    const float* fin_ab = (const float*)d_in[25];
    const float* fin_aq = (const float*)d_in[26];
    const float* W_out  = (const float*)d_in[27];
    const float* b_out  = (const float*)d_in[28];

    float *partb, *z3, *z2, *zii, *relagg, *itemitem;
    uint32_t *h0p, *h1p, *ictp;
    cudaGetSymbolAddress((void**)&h0p, g_h0p);
    cudaGetSymbolAddress((void**)&h1p, g_h1p);
    cudaGetSymbolAddress((void**)&ictp, g_ictp);
    cudaGetSymbolAddress((void**)&partb, g_part);
    cudaGetSymbolAddress((void**)&z3, g_z3);
    cudaGetSymbolAddress((void**)&z2, g_z2);
    cudaGetSymbolAddress((void**)&zii, g_zii);
    cudaGetSymbolAddress((void**)&relagg,   g_relagg);
    cudaGetSymbolAddress((void**)&itemitem, g_itemitem);

    EncodeTiledFn enc = nullptr;
    {
        void* fp = nullptr;
        cudaDriverEntryPointQueryResult qr;
        cudaGetDriverEntryPoint("cuTensorMapEncodeTiled", &fp,
                                cudaEnableDefault, &qr);
        enc = (EncodeTiledFn)fp;
    }
    CUtensorMap tm_mp, tm_ui, tm_ii;
    make_adj_map(enc, &tm_mp, adj_mp, 3);
    make_adj_map(enc, &tm_ui, adj_ui, 2);
    make_adj_map(enc, &tm_ii, adj_ii, 2);

    cudaFuncSetAttribute(spmm_kernel,
                         cudaFuncAttributeMaxDynamicSharedMemorySize, SPMM_SMEM_BYTES);
    const int FIN_SMEM = (8192 + 2048 + 2048 + 1024 + 128 + 128 + 32 + 64) * 4;
    cudaFuncSetAttribute(final_kernel,
                         cudaFuncAttributeMaxDynamicSharedMemorySize, FIN_SMEM);

    dim3 blk64x4(64, 4);

    // Stage 1: feature mapping (fused pack)
    map_kernel<<<N_NODES / 4, blk64x4>>>(feat_item, W_map0, b_map0, h0p);
    map_kernel<<<N_NODES / 4, blk64x4>>>(feat_user, W_map1, b_map1, h1p);

    // Stage 2: phase-A GEMMs (3x adj_mp@h0 + 2x adj_ui@h1), split-K=3
    spmm_kernel<<<dim3(N_NODES / BM, 5, 3), 256, SPMM_SMEM_BYTES>>>(
        tm_mp, tm_ui, 3, h0p, h1p, partb, N_NODES / 3);

    // Stage 3: reduce+transform, then attention pooling
    relz_kernel<<<dim3(N_NODES / 16, 3), blk64x4>>>(
        partb, 5, 3, 0, W_rel, b_rel, z3, HID * HID, HID);
    relz_kernel<<<dim3(N_NODES / 16, 2), blk64x4>>>(
        partb, 5, 3, 3, W_sch, b_sch, z2, 0, 0);
    attn_kernel<<<N_NODES, 128>>>(z3, rel_aW, rel_ab, rel_aq, relagg, nullptr, 3);
    attn_kernel<<<N_NODES, 128>>>(z2, sch_aW, sch_ab, sch_aq, nullptr, (__half*)ictp, 2);

    // Stage 4: phase-B GEMMs (2x adj_ii@itemcls), split-K=3
    spmm_kernel<<<dim3(N_NODES / BM, 2, 3), 256, SPMM_SMEM_BYTES>>>(
        tm_ii, tm_ii, 2, ictp, ictp, partb, N_NODES / 3);

    // Stage 5: reduce+transform + attention (item-item)
    relz_kernel<<<dim3(N_NODES / 16, 2), blk64x4>>>(
        partb, 2, 3, 0, W_ii, b_ii, zii, HID * HID, HID);
    attn_kernel<<<N_NODES, 128>>>(zii, ii_aW, ii_ab, ii_aq, itemitem, nullptr, 2);

    // Stage 6: fused final attention + projection
    final_kernel<<<N_NODES / 16, 256, FIN_SMEM>>>(
        relagg, itemitem, fin_aW, fin_ab, fin_aq,
        W_out, b_out, (float*)d_out, out_size);
}

// round 17
// speedup vs baseline: 1.1434x; 1.0040x over previous
#include <cuda_runtime.h>
#include <cuda.h>
#include <cuda_fp16.h>
#include <math.h>
#include <stdint.h>

#define N_NODES 6144
#define D_IN    256
#define HID     64
#define OUT_DIM 32
#define ATT_H   128

#define ADJ_SCALE   2048.0f
#define ADJ_UNSCALE 4.8828125e-4f   // 1/2048

// ---------------- scratch (device globals; no allocation allowed) ----------
__device__ uint32_t g_h0p[N_NODES * HID / 2];
__device__ uint32_t g_h1p[N_NODES * HID / 2];
__device__ uint32_t g_ictp[N_NODES * HID / 2];
__device__ float g_part[15 * N_NODES * HID];
__device__ float g_z3[3 * N_NODES * HID];
__device__ float g_z2[2 * N_NODES * HID];
__device__ float g_zii[2 * N_NODES * HID];
__device__ float g_relagg  [N_NODES * HID];
__device__ float g_itemitem[N_NODES * HID];

// ---------------- helpers -----------------------------------------------------
__device__ __forceinline__ uint32_t smem_u32(const void* p) {
    uint32_t a;
    asm("{ .reg .u64 t; cvta.to.shared.u64 t, %1; cvt.u32.u64 %0, t; }"
        : "=r"(a) : "l"(p));
    return a;
}
__device__ __forceinline__ float tanha(float x) {   // HW tanh (scores only)
    float y;
    asm("tanh.approx.f32 %0, %1;" : "=f"(y) : "f"(x));
    return y;
}
__device__ __forceinline__ uint32_t pack_f16x2(float lo, float hi) {
    uint32_t r;
    asm("cvt.rn.f16x2.f32 %0, %1, %2;" : "=r"(r) : "f"(hi), "f"(lo));
    return r;
}
__device__ __forceinline__ uint32_t ld_scale_pack(const float* p) {
    float2 v = *(const float2*)p;
    return pack_f16x2(v.x * ADJ_SCALE, v.y * ADJ_SCALE);
}
__device__ __forceinline__ void mma_fp16(float* c, const uint32_t* a, const uint32_t* b) {
    asm("mma.sync.aligned.m16n8k16.row.col.f32.f16.f16.f32 "
        "{%0,%1,%2,%3}, {%4,%5,%6,%7}, {%8,%9}, {%0,%1,%2,%3};"
        : "+f"(c[0]), "+f"(c[1]), "+f"(c[2]), "+f"(c[3])
        : "r"(a[0]), "r"(a[1]), "r"(a[2]), "r"(a[3]),
          "r"(b[0]), "r"(b[1]));
}
__device__ __forceinline__ void cp16(void* dst, const void* src) {
    uint32_t d = (uint32_t)__cvta_generic_to_shared(dst);
    asm volatile("cp.async.cg.shared.global [%0], [%1], 16;" :: "r"(d), "l"(src));
}
__device__ __forceinline__ void cp_commit() {
    asm volatile("cp.async.commit_group;" ::: "memory");
}
__device__ __forceinline__ void cp_wait1() {
    asm volatile("cp.async.wait_group 1;" ::: "memory");
}
__device__ __forceinline__ void mbar_init(uint32_t addr, uint32_t cnt) {
    asm volatile("mbarrier.init.shared.b64 [%0], %1;" :: "r"(addr), "r"(cnt) : "memory");
}
__device__ __forceinline__ void mbar_expect_tx(uint32_t addr, uint32_t bytes) {
    asm volatile("mbarrier.arrive.expect_tx.shared.b64 _, [%0], %1;"
                 :: "r"(addr), "r"(bytes) : "memory");
}
__device__ __forceinline__ void mbar_wait(uint32_t addr, uint32_t parity) {
    uint32_t done;
    asm volatile(
        "{ .reg .pred p; mbarrier.try_wait.parity.acquire.cta.shared::cta.b64 p, [%1], %2;"
        " selp.b32 %0, 1, 0, p; }"
        : "=r"(done) : "r"(addr), "r"(parity) : "memory");
    if (!done) {
        asm volatile(
            "{ .reg .pred P1;\n"
            "WL_%=: mbarrier.try_wait.parity.acquire.cta.shared::cta.b64 P1, [%0], %1, 0x989680;\n"
            "@P1 bra.uni WD_%=;\n"
            "bra.uni WL_%=;\n"
            "WD_%=: }"
            :: "r"(addr), "r"(parity) : "memory");
    }
}
__device__ __forceinline__ void tma_load_a(
    const CUtensorMap* tm, uint32_t dst, int x, int y, int z, uint32_t mbar)
{
    asm volatile(
        "cp.async.bulk.tensor.3d.shared::cta.global.tile.mbarrier::complete_tx::bytes "
        "[%0], [%1, {%2, %3, %4}], [%5];"
        :: "r"(dst), "l"(tm), "r"(x), "r"(y), "r"(z), "r"(mbar)
        : "memory");
}

// ---------------- feature mapping + fp16 pack --------------------------------
__global__ void __launch_bounds__(256) map_kernel(
    const float* __restrict__ feat, const float* __restrict__ W,
    const float* __restrict__ b, uint32_t* __restrict__ outp)
{
    __shared__ float hs[4][HID];
    int tx = threadIdx.x, ty = threadIdx.y;
    int row = blockIdx.x * 4 + ty;
    const float* fr = feat + (size_t)row * D_IN;
    float acc = b[tx];
#pragma unroll 8
    for (int k = 0; k < D_IN; k++)
        acc = fmaf(fr[k], W[k * HID + tx], acc);
    hs[ty][tx] = tanhf(acc);
    __syncthreads();
    int tid = ty * 64 + tx;
    if (tid < 128) {
        int pr = tid >> 6, c = tid & 63;
        outp[(size_t)(blockIdx.x * 2 + pr) * HID + c] =
            pack_f16x2(hs[2 * pr][c], hs[2 * pr + 1][c]);
    }
}

// ---------------- big GEMM: wide K-tiles (2x TMA boxes), 2 CTA/SM (R16) ------
#define BM 128
#define BK 32
#define NSUB 2
#define BKO (BK * NSUB)
#define HS_STRIDE 72
#define STAGES 2
#define A_SUB_BYTES (BM * 128)
#define A_TILE_BYTES (NSUB * A_SUB_BYTES)
#define H_STAGE_WORDS (NSUB * 16 * HS_STRIDE)
#define H_STAGE_BYTES (H_STAGE_WORDS * 4)
#define A_OFF 1024
#define H_OFF (A_OFF + STAGES * A_TILE_BYTES)
#define SPMM_SMEM_BYTES (H_OFF + STAGES * H_STAGE_BYTES)

__device__ __forceinline__ void spmm_load_h(
    const uint32_t* __restrict__ Hp, uint32_t* hs, int k0, int tid)
{
#pragma unroll
    for (int i = 0; i < 2; i++) {
        int idx = tid + i * 256;
        int r   = idx >> 4;
        int c4  = (idx & 15) << 2;
        cp16(hs + r * HS_STRIDE + c4, Hp + (size_t)((k0 >> 1) + r) * HID + c4);
    }
}

__global__ void __launch_bounds__(256, 2) spmm_kernel(
    const __grid_constant__ CUtensorMap tmA,
    const __grid_constant__ CUtensorMap tmB,
    int nA, const uint32_t* __restrict__ hA, const uint32_t* __restrict__ hB,
    float* __restrict__ part, int kPerSplit)
{
    extern __shared__ __align__(1024) char smem[];
    uint32_t sbase = smem_u32(smem);

    int b = blockIdx.y;
    const CUtensorMap* tm;
    const uint32_t* Hp;
    int zc;
    if (b < nA) { tm = &tmA; zc = b;      Hp = hA; }
    else        { tm = &tmB; zc = b - nA; Hp = hB; }

    float* Cb = part + ((size_t)blockIdx.z * gridDim.y + b) * (size_t)(N_NODES * HID);
    uint32_t* HsBase = (uint32_t*)(smem + H_OFF);

    int tid  = threadIdx.x;
    int lane = tid & 31;
    int warp = tid >> 5;
    int g = lane >> 2;
    int t = lane & 3;
    int wm = (warp & 3) * 32;
    int wn = (warp >> 2) * 32;
    int row0 = blockIdx.x * BM;
    int kbeg = blockIdx.z * kPerSplit;
    int nt = kPerSplit / BKO;

    if (tid == 0)
        for (int s = 0; s < STAGES; s++)
            mbar_init(sbase + s * 8, 1);
    __syncthreads();

    float acc[2][4][4];
#pragma unroll
    for (int mt = 0; mt < 2; mt++)
#pragma unroll
        for (int ntl = 0; ntl < 4; ntl++)
#pragma unroll
            for (int i = 0; i < 4; i++) acc[mt][ntl][i] = 0.f;

    if (tid == 0) {
        mbar_expect_tx(sbase, A_TILE_BYTES);
#pragma unroll
        for (int s = 0; s < NSUB; s++)
            tma_load_a(tm, sbase + A_OFF + s * A_SUB_BYTES,
                       kbeg + s * BK, row0, zc, sbase);
    }
    spmm_load_h(Hp, HsBase, kbeg, tid);
    cp_commit();

    for (int j = 0; j < nt; j++) {
        if (j + 1 < nt) {
            int st = (j + 1) & 1;
            int k1 = kbeg + (j + 1) * BKO;
            if (tid == 0) {
                mbar_expect_tx(sbase + st * 8, A_TILE_BYTES);
#pragma unroll
                for (int s = 0; s < NSUB; s++)
                    tma_load_a(tm, sbase + A_OFF + st * A_TILE_BYTES + s * A_SUB_BYTES,
                               k1 + s * BK, row0, zc, sbase + st * 8);
            }
            spmm_load_h(Hp, HsBase + st * H_STAGE_WORDS, k1, tid);
        }
        cp_commit();

        mbar_wait(sbase + (j & 1) * 8, (j >> 1) & 1);
        cp_wait1();
        __syncthreads();

        const char*     aStage = smem + A_OFF + (j & 1) * A_TILE_BYTES;
        const uint32_t* hStage = HsBase + (j & 1) * H_STAGE_WORDS;

#pragma unroll
        for (int sub = 0; sub < NSUB; sub++) {
            const char*     as = aStage + sub * A_SUB_BYTES;
            const uint32_t* hs = hStage + sub * 16 * HS_STRIDE;
#pragma unroll
            for (int c = 0; c < 2; c++) {
                int kk  = c * 16;
                int kp0 = c * 8;
                uint32_t bf[4][2];
#pragma unroll
                for (int ntl = 0; ntl < 4; ntl++) {
                    int col = wn + ntl * 8 + g;
                    bf[ntl][0] = hs[(kp0 + t)     * HS_STRIDE + col];
                    bf[ntl][1] = hs[(kp0 + t + 4) * HS_STRIDE + col];
                }
#pragma unroll
                for (int mt = 0; mt < 2; mt++) {
                    int r0l = wm + mt * 16 + g;
                    int r1l = r0l + 8;
                    uint32_t m0 = (uint32_t)(r0l & 7) << 4;
                    uint32_t m1 = (uint32_t)(r1l & 7) << 4;
                    uint32_t base0 = (uint32_t)(r0l * 128 + (kk + 2 * t) * 4);
                    uint32_t base1 = (uint32_t)(r1l * 128 + (kk + 2 * t) * 4);
                    uint32_t af[4];
                    af[0] = ld_scale_pack((const float*)(as + (base0 ^ m0)));
                    af[1] = ld_scale_pack((const float*)(as + (base1 ^ m1)));
                    af[2] = ld_scale_pack((const float*)(as + ((base0 + 32) ^ m0)));
                    af[3] = ld_scale_pack((const float*)(as + ((base1 + 32) ^ m1)));
#pragma unroll
                    for (int ntl = 0; ntl < 4; ntl++)
                        mma_fp16(acc[mt][ntl], af, bf[ntl]);
                }
            }
        }
        __syncthreads();
    }

#pragma unroll
    for (int mt = 0; mt < 2; mt++) {
        int r_lo = row0 + wm + mt * 16 + g;
#pragma unroll
        for (int ntl = 0; ntl < 4; ntl++) {
            int col = wn + ntl * 8 + 2 * t;
            *(float2*)&Cb[(size_t)r_lo * HID + col] =
                make_float2(acc[mt][ntl][0] * ADJ_UNSCALE,
                            acc[mt][ntl][1] * ADJ_UNSCALE);
            *(float2*)&Cb[(size_t)(r_lo + 8) * HID + col] =
                make_float2(acc[mt][ntl][2] * ADJ_UNSCALE,
                            acc[mt][ntl][3] * ADJ_UNSCALE);
        }
    }
}

// ---------------- fused split-K reduce + transform (R16 version) -------------
__global__ void __launch_bounds__(256) relz_kernel(
    const float* __restrict__ part, int NB, int KS, int batch0,
    const float* __restrict__ W, const float* __restrict__ bias,
    float* __restrict__ Z, int wStride, int bStride)
{
    int batch = batch0 + blockIdx.y;
    const float* Wb = W + (size_t)blockIdx.y * wStride;
    const float* bb = bias + (size_t)blockIdx.y * bStride;
    float* Zb = Z + (size_t)blockIdx.y * N_NODES * HID;

    __shared__ float Ws[HID * HID];
    __shared__ float xs[16][HID];

    int tx = threadIdx.x, ty = threadIdx.y;
    int tid = ty * 64 + tx;
    for (int i = tid; i < HID * HID; i += 256)
        Ws[i] = Wb[i];

    int row0 = blockIdx.x * 16;
    const size_t slab = (size_t)N_NODES * HID;
#pragma unroll
    for (int i = 0; i < 4; i++) {
        int idx = tid + i * 256;
        int r = idx >> 6, c = idx & 63;
        float v = 0.f;
        for (int s = 0; s < KS; s++)
            v += part[(size_t)(s * NB + batch) * slab + (size_t)(row0 + r) * HID + c];
        xs[r][c] = v;
    }
    __syncthreads();

    float acc0 = bb[tx], acc1 = acc0, acc2 = acc0, acc3 = acc0;
    int rb = ty * 4;
#pragma unroll
    for (int k = 0; k < HID; k += 4) {
        float w0 = Ws[(k + 0) * HID + tx];
        float w1 = Ws[(k + 1) * HID + tx];
        float w2 = Ws[(k + 2) * HID + tx];
        float w3 = Ws[(k + 3) * HID + tx];
        float4 x0 = *(const float4*)&xs[rb + 0][k];
        float4 x1 = *(const float4*)&xs[rb + 1][k];
        float4 x2 = *(const float4*)&xs[rb + 2][k];
        float4 x3 = *(const float4*)&xs[rb + 3][k];
        acc0 = fmaf(x0.x, w0, fmaf(x0.y, w1, fmaf(x0.z, w2, fmaf(x0.w, w3, acc0))));
        acc1 = fmaf(x1.x, w0, fmaf(x1.y, w1, fmaf(x1.z, w2, fmaf(x1.w, w3, acc1))));
        acc2 = fmaf(x2.x, w0, fmaf(x2.y, w1, fmaf(x2.z, w2, fmaf(x2.w, w3, acc2))));
        acc3 = fmaf(x3.x, w0, fmaf(x3.y, w1, fmaf(x3.z, w2, fmaf(x3.w, w3, acc3))));
    }
    Zb[(size_t)(row0 + rb + 0) * HID + tx] = tanhf(acc0);
    Zb[(size_t)(row0 + rb + 1) * HID + tx] = tanhf(acc1);
    Zb[(size_t)(row0 + rb + 2) * HID + tx] = tanhf(acc2);
    Zb[(size_t)(row0 + rb + 3) * HID + tx] = tanhf(acc3);
}

// ---------------- attention pooling: 4 nodes/block (R14 version) -------------
__global__ void __launch_bounds__(256) attn_kernel(
    const float* __restrict__ Z, const float* __restrict__ aW,
    const float* __restrict__ ab, const float* __restrict__ aq,
    float* __restrict__ outF, __half* __restrict__ outP, int K)
{
    __shared__ float saW[HID * ATT_H];
    __shared__ float zs[4][3 * HID];
    __shared__ float prt[4][2][3];

    int tid = threadIdx.x;
    int n0 = blockIdx.x * 4;

    for (int i = tid; i < HID * ATT_H; i += 256) saW[i] = aW[i];
    for (int i = tid; i < 4 * K * HID; i += 256) {
        int node = i / (K * HID);
        int rem  = i - node * K * HID;
        int k = rem >> 6, d = rem & 63;
        zs[node][k * HID + d] = Z[((size_t)k * N_NODES + n0 + node) * HID + d];
    }
    __syncthreads();

    int w = tid >> 5, lane = tid & 31;
    int node = w >> 1, half = w & 1;
    int c0 = half * 64 + lane;

    float ab0 = ab[c0], ab1 = ab[c0 + 32];
    float q0  = aq[c0], q1  = aq[c0 + 32];
    for (int k = 0; k < K; k++) {
        const float* zr = &zs[node][k * HID];
        float u0 = ab0, u1 = ab1;
#pragma unroll 8
        for (int d = 0; d < HID; d++) {
            float zv = zr[d];
            u0 = fmaf(zv, saW[d * ATT_H + c0], u0);
            u1 = fmaf(zv, saW[d * ATT_H + c0 + 32], u1);
        }
        float p = tanha(u0) * q0 + tanha(u1) * q1;
#pragma unroll
        for (int m = 16; m >= 1; m >>= 1)
            p += __shfl_xor_sync(0xffffffffu, p, m);
        if (lane == 0) prt[node][half][k] = p;
    }
    __syncthreads();

    float sc[3], mx = -1e30f;
    for (int k = 0; k < K; k++) {
        sc[k] = prt[node][0][k] + prt[node][1][k];
        mx = fmaxf(mx, sc[k]);
    }
    float e[3], den = 0.f;
    for (int k = 0; k < K; k++) { e[k] = expf(sc[k] - mx); den += e[k]; }

    int col = half * 32 + lane;
    float o = 0.f;
    for (int k = 0; k < K; k++)
        o += (e[k] / den) * zs[node][k * HID + col];
    int n = n0 + node;
    if (outF) outF[(size_t)n * HID + col] = o;
    if (outP) outP[((size_t)(n >> 1) * HID + col) * 2 + (n & 1)] = __float2half_rn(o);
}

// ---------------- fused final: attention over 2 + projection -----------------
__global__ void __launch_bounds__(256) final_kernel(
    const float* __restrict__ Hrel, const float* __restrict__ Hii,
    const float* __restrict__ aW, const float* __restrict__ ab,
    const float* __restrict__ aq, const float* __restrict__ Wout,
    const float* __restrict__ bout, float* __restrict__ out, int out_total)
{
    extern __shared__ float sm[];
    float* saW = sm;
    float* sWo = saW + 8192;
    float* sz  = sWo + 2048;
    float* spl = sz + 2048;
    float* sab = spl + 1024;
    float* sq  = sab + 128;
    float* sbo = sq + 128;
    float* ss  = sbo + 32;

    int tid = threadIdx.x;
    for (int i = tid; i < 8192; i += 256) saW[i] = aW[i];
    for (int i = tid; i < 2048; i += 256) sWo[i] = Wout[i];
    if (tid < 128) { sab[tid] = ab[tid]; sq[tid] = aq[tid]; }
    if (tid < 32)  sbo[tid] = bout[tid];

    int row0 = blockIdx.x * 16;
#pragma unroll
    for (int i = 0; i < 8; i++) {
        int idx = tid + i * 256;
        int k = idx >> 10, rem = idx & 1023;
        int rr = rem >> 6, c = rem & 63;
        const float* src = k ? Hii : Hrel;
        sz[k * 1024 + rr * 64 + c] = src[(size_t)(row0 + rr) * HID + c];
    }
    __syncthreads();

    {
        int row = tid >> 4, seg = tid & 15, j0 = seg * 8;
        for (int r = 0; r < 2; r++) {
            const float* zr = sz + r * 1024 + row * 64;
            float u[8];
#pragma unroll
            for (int jj = 0; jj < 8; jj++) u[jj] = sab[j0 + jj];
#pragma unroll 4
            for (int d = 0; d < 64; d++) {
                float zv = zr[d];
                float4 wA = *(const float4*)&saW[d * 128 + j0];
                float4 wB = *(const float4*)&saW[d * 128 + j0 + 4];
                u[0] = fmaf(zv, wA.x, u[0]); u[1] = fmaf(zv, wA.y, u[1]);
                u[2] = fmaf(zv, wA.z, u[2]); u[3] = fmaf(zv, wA.w, u[3]);
                u[4] = fmaf(zv, wB.x, u[4]); u[5] = fmaf(zv, wB.y, u[5]);
                u[6] = fmaf(zv, wB.z, u[6]); u[7] = fmaf(zv, wB.w, u[7]);
            }
            float partial = 0.f;
#pragma unroll
            for (int jj = 0; jj < 8; jj++)
                partial += tanha(u[jj]) * sq[j0 + jj];
#pragma unroll
            for (int m = 8; m >= 1; m >>= 1)
                partial += __shfl_xor_sync(0xffffffffu, partial, m);
            if (seg == 0) ss[row * 4 + r] = partial;
        }
    }
    __syncthreads();

    {
        int tx = tid & 63, qy = tid >> 6;
#pragma unroll
        for (int i = 0; i < 4; i++) {
            int rr = qy * 4 + i;
            float s0 = ss[rr * 4 + 0], s1 = ss[rr * 4 + 1];
            float mx = fmaxf(s0, s1);
            float e0 = expf(s0 - mx), e1 = expf(s1 - mx);
            float den = e0 + e1;
            float o = (e0 / den) * sz[rr * 64 + tx] + (e1 / den) * sz[1024 + rr * 64 + tx];
            spl[rr * 64 + tx] = o;
            if (out_total > N_NODES * OUT_DIM)
                out[(size_t)N_NODES * OUT_DIM + (size_t)(row0 + rr) * HID + tx] = o;
        }
    }
    __syncthreads();

    {
        int row = tid >> 4;
        int c0 = tid & 15;
        const float* pr = spl + row * 64;
        float acc0 = sbo[c0], acc1 = sbo[c0 + 16];
#pragma unroll
        for (int d = 0; d < 64; d++) {
            float pv = pr[d];
            acc0 = fmaf(pv, sWo[d * 32 + c0], acc0);
            acc1 = fmaf(pv, sWo[d * 32 + c0 + 16], acc1);
        }
        out[(size_t)(row0 + row) * OUT_DIM + c0]      = acc0;
        out[(size_t)(row0 + row) * OUT_DIM + c0 + 16] = acc1;
    }
}

// ---------------- host: tensor map creation ----------------------------------
typedef CUresult (*EncodeTiledFn)(
    CUtensorMap*, CUtensorMapDataType, cuuint32_t, void*,
    const cuuint64_t*, const cuuint64_t*, const cuuint32_t*, const cuuint32_t*,
    CUtensorMapInterleave, CUtensorMapSwizzle, CUtensorMapL2promotion,
    CUtensorMapFloatOOBfill);

static void make_adj_map(EncodeTiledFn enc, CUtensorMap* tm, const void* base, int nb)
{
    cuuint64_t dims[3]    = { N_NODES, N_NODES, (cuuint64_t)nb };
    cuuint64_t strides[2] = { (cuuint64_t)N_NODES * 4,
                              (cuuint64_t)N_NODES * N_NODES * 4 };
    cuuint32_t box[3]     = { BK, BM, 1 };
    cuuint32_t estr[3]    = { 1, 1, 1 };
    enc(tm, CU_TENSOR_MAP_DATA_TYPE_FLOAT32, 3, (void*)base,
        dims, strides, box, estr,
        CU_TENSOR_MAP_INTERLEAVE_NONE, CU_TENSOR_MAP_SWIZZLE_128B,
        CU_TENSOR_MAP_L2_PROMOTION_L2_256B, CU_TENSOR_MAP_FLOAT_OOB_FILL_NONE);
}

// ---------------- launch ----------------------------------------------------
extern "C" void kernel_launch(void* const* d_in, const int* in_sizes, int n_in,
                              void* d_out, int out_size)
{
    const float* feat_item = (const float*)d_in[0];
    const float* feat_user = (const float*)d_in[1];
    const float* adj_ii    = (const float*)d_in[2];
    const float* adj_mp    = (const float*)d_in[3];
    const float* adj_ui    = (const float*)d_in[4];
    const float* W_map0 = (const float*)d_in[5];
    const float* b_map0 = (const float*)d_in[6];
    const float* W_map1 = (const float*)d_in[7];
    const float* b_map1 = (const float*)d_in[8];
    const float* W_rel  = (const float*)d_in[9];
    const float* b_rel  = (const float*)d_in[10];
    const float* rel_aW = (const float*)d_in[11];
    const float* rel_ab = (const float*)d_in[12];
    const float* rel_aq = (const float*)d_in[13];
    const float* W_sch  = (const float*)d_in[14];
    const float* b_sch  = (const float*)d_in[15];
    const float* sch_aW = (const float*)d_in[16];
    const float* sch_ab = (const float*)d_in[17];
    const float* sch_aq = (const float*)d_in[18];
    const float* W_ii   = (const float*)d_in[19];
    const float* b_ii   = (const float*)d_in[20];
    const float* ii_aW  = (const float*)d_in[21];
    const float* ii_ab  = (const float*)d_in[22];
    const float* ii_aq  = (const float*)d_in[23];
    const float* fin_aW = (const float*)d_in[24];
    const float* fin_ab = (const float*)d_in[25];
    const float* fin_aq = (const float*)d_in[26];
    const float* W_out  = (const float*)d_in[27];
    const float* b_out  = (const float*)d_in[28];

    float *partb, *z3, *z2, *zii, *relagg, *itemitem;
    uint32_t *h0p, *h1p, *ictp;
    cudaGetSymbolAddress((void**)&h0p, g_h0p);
    cudaGetSymbolAddress((void**)&h1p, g_h1p);
    cudaGetSymbolAddress((void**)&ictp, g_ictp);
    cudaGetSymbolAddress((void**)&partb, g_part);
    cudaGetSymbolAddress((void**)&z3, g_z3);
    cudaGetSymbolAddress((void**)&z2, g_z2);
    cudaGetSymbolAddress((void**)&zii, g_zii);
    cudaGetSymbolAddress((void**)&relagg,   g_relagg);
    cudaGetSymbolAddress((void**)&itemitem, g_itemitem);

    EncodeTiledFn enc = nullptr;
    {
        void* fp = nullptr;
        cudaDriverEntryPointQueryResult qr;
        cudaGetDriverEntryPoint("cuTensorMapEncodeTiled", &fp,
                                cudaEnableDefault, &qr);
        enc = (EncodeTiledFn)fp;
    }
    CUtensorMap tm_mp, tm_ui, tm_ii;
    make_adj_map(enc, &tm_mp, adj_mp, 3);
    make_adj_map(enc, &tm_ui, adj_ui, 2);
    make_adj_map(enc, &tm_ii, adj_ii, 2);

    cudaFuncSetAttribute(spmm_kernel,
                         cudaFuncAttributeMaxDynamicSharedMemorySize, SPMM_SMEM_BYTES);
    const int FIN_SMEM = (8192 + 2048 + 2048 + 1024 + 128 + 128 + 32 + 64) * 4;
    cudaFuncSetAttribute(final_kernel,
                         cudaFuncAttributeMaxDynamicSharedMemorySize, FIN_SMEM);

    dim3 blk64x4(64, 4);

    // Stage 1: feature mapping (fused pack)
    map_kernel<<<N_NODES / 4, blk64x4>>>(feat_item, W_map0, b_map0, h0p);
    map_kernel<<<N_NODES / 4, blk64x4>>>(feat_user, W_map1, b_map1, h1p);

    // Stage 2: phase-A GEMMs (3x adj_mp@h0 + 2x adj_ui@h1), split-K=3
    spmm_kernel<<<dim3(N_NODES / BM, 5, 3), 256, SPMM_SMEM_BYTES>>>(
        tm_mp, tm_ui, 3, h0p, h1p, partb, N_NODES / 3);

    // Stage 3: reduce+transform, then attention pooling
    relz_kernel<<<dim3(N_NODES / 16, 3), blk64x4>>>(
        partb, 5, 3, 0, W_rel, b_rel, z3, HID * HID, HID);
    relz_kernel<<<dim3(N_NODES / 16, 2), blk64x4>>>(
        partb, 5, 3, 3, W_sch, b_sch, z2, 0, 0);
    attn_kernel<<<N_NODES / 4, 256>>>(z3, rel_aW, rel_ab, rel_aq, relagg, nullptr, 3);
    attn_kernel<<<N_NODES / 4, 256>>>(z2, sch_aW, sch_ab, sch_aq, nullptr, (__half*)ictp, 2);

    // Stage 4: phase-B GEMMs (2x adj_ii@itemcls), split-K=3
    spmm_kernel<<<dim3(N_NODES / BM, 2, 3), 256, SPMM_SMEM_BYTES>>>(
        tm_ii, tm_ii, 2, ictp, ictp, partb, N_NODES / 3);

    // Stage 5: reduce+transform + attention (item-item)
    relz_kernel<<<dim3(N_NODES / 16, 2), blk64x4>>>(
        partb, 2, 3, 0, W_ii, b_ii, zii, HID * HID, HID);
    attn_kernel<<<N_NODES / 4, 256>>>(zii, ii_aW, ii_ab, ii_aq, itemitem, nullptr, 2);

    // Stage 6: fused final attention + projection
    final_kernel<<<N_NODES / 16, 256, FIN_SMEM>>>(
        relagg, itemitem, fin_aW, fin_ab, fin_aq,
        W_out, b_out, (float*)d_out, out_size);
}